// round 5
// baseline (speedup 1.0000x reference)
#include <cuda_runtime.h>

#define SEQ   600
#define BATCH 4096
#define INP   6
#define HID   30
#define OUTD  61
#define UPAD  32              // padded units
#define VLEN  36              // fused state vector: 6 x + 30 h
#define NQ    9               // 36/4 quads
#define SVS   44              // v row stride in floats (16B-aligned rows)
#define BBLK  32              // batch rows per block
#define NBLK  (BATCH / BBLK)  // 128
#define NTHR  1024
#define NDOM  8               // barrier domains (4 batches each)
#define DOMB  4
#define DTHR  128

typedef unsigned long long ull;

// ---------------- preprocessed weights (device globals) ----------------
__device__ __align__(16) float g_W[4][UPAD][VLEN];  // [gate][unit][ Wih(6) | Whh(30) ]
__device__ float g_bias[4][UPAD];                   // b_ih + b_hh (0 for pad units)
__device__ float g_M[HID][OUTD];                    // fused fc1+fc2
__device__ float g_bv[OUTD];                        // b2 + b1 @ W2^T

// ---------------- helpers ----------------
__device__ __forceinline__ void ffma2(ull& acc, ull a, ull b) {
    asm("fma.rn.f32x2 %0, %1, %2, %0;" : "+l"(acc) : "l"(a), "l"(b));
}
__device__ __forceinline__ ull pack2(float x, float y) {
    ull r; asm("mov.b64 %0, {%1, %2};" : "=l"(r) : "f"(x), "f"(y)); return r;
}
__device__ __forceinline__ float hsum2(ull v) {
    float2 r; asm("mov.b64 {%0, %1}, %2;" : "=f"(r.x), "=f"(r.y) : "l"(v));
    return r.x + r.y;
}
__device__ __forceinline__ float tanh_fast(float x) {
    float r; asm("tanh.approx.f32 %0, %1;" : "=f"(r) : "f"(x)); return r;
}
// predicated shared store (pure @p STS, no branch/BSSY)
__device__ __forceinline__ void sts_if(int pred, float* addr, float val) {
    unsigned sa = (unsigned)__cvta_generic_to_shared(addr);
    asm volatile("{ .reg .pred p; setp.ne.b32 p, %0, 0; @p st.shared.f32 [%1], %2; }"
                 :: "r"(pred), "r"(sa), "f"(val) : "memory");
}

// ---------------- prep kernel ----------------
__global__ void prep_kernel(const float* __restrict__ Wih, const float* __restrict__ Whh,
                            const float* __restrict__ bih, const float* __restrict__ bhh,
                            const float* __restrict__ W1,  const float* __restrict__ b1,
                            const float* __restrict__ W2,  const float* __restrict__ b2) {
    int tid = threadIdx.x;
    for (int idx = tid; idx < 4 * UPAD * VLEN; idx += blockDim.x) {
        int g = idx / (UPAD * VLEN);
        int r = idx % (UPAD * VLEN);
        int u = r / VLEN, j = r % VLEN;
        float w = 0.0f;
        if (u < HID) {
            if (j < INP) w = Wih[(g * HID + u) * INP + j];
            else         w = Whh[(g * HID + u) * HID + (j - INP)];
        }
        g_W[g][u][j] = w;
    }
    for (int idx = tid; idx < 4 * UPAD; idx += blockDim.x) {
        int g = idx / UPAD, u = idx % UPAD;
        g_bias[g][u] = (u < HID) ? (bih[g * HID + u] + bhh[g * HID + u]) : 0.0f;
    }
    for (int idx = tid; idx < HID * OUTD; idx += blockDim.x) {
        int j = idx / OUTD, o = idx % OUTD;
        float s = 0.0f;
        for (int k = 0; k < HID; k++) s += W1[k * HID + j] * W2[o * HID + k];
        g_M[j][o] = s;
    }
    for (int o = tid; o < OUTD; o += blockDim.x) {
        float s = b2[o];
        for (int k = 0; k < HID; k++) s += b1[k] * W2[o * HID + k];
        g_bv[o] = s;
    }
}

// ---------------- per-domain X stager: 4 batches = 24 floats = 6 float4 ----------------
__device__ __forceinline__ void stage_x(const float* __restrict__ X, int t, int bfirst,
                                        int lt, float* __restrict__ vbuf, int bgb) {
    if (lt < 6) {  // offset (t*4096 + bfirst)*6 floats: bfirst mult of 4 -> 96B-aligned
        const float* p = X + ((size_t)t * BATCH + bfirst) * INP;
        float4 v = *(const float4*)(p + lt * 4);
        int lin = lt * 4;
        float vv[4] = {v.x, v.y, v.z, v.w};
#pragma unroll
        for (int m = 0; m < 4; m++) {
            int e = lin + m;
            int b = e / INP, i = e % INP;
            vbuf[(bgb + b) * SVS + i] = vv[m];
        }
    }
}

// ---------------- main persistent LSTM kernel ----------------
__global__ void __launch_bounds__(NTHR, 1)
lstm_kernel(const float* __restrict__ X, float* __restrict__ out) {
    __shared__ __align__(16) float sv[2][BBLK][SVS];   // 11264 B, v = [x|h] double buffer

    const int tid   = threadIdx.x;
    const int dom   = tid >> 7;            // batch domain 0..7 (warps 4d..4d+3)
    const int lt    = tid & (DTHR - 1);
    const int lane  = tid & 31;
    const int g     = lane >> 3;           // gate 0..3 (i,f,g,o)
    const int u_lo  = lane & 7;
    const int u_hi  = (tid >> 5) & 3;
    const int u     = u_hi * 8 + u_lo;     // unit 0..31
    const int bbase = blockIdx.x * BBLK;
    const int bgb   = dom * DOMB;          // domain's first batch row in sv
    const int barid = 1 + dom;

    // weights for (g,u) into registers: 18 ull = 36 floats
    ull w[18];
    {
        const ull* wp = (const ull*)&g_W[g][u][0];
#pragma unroll
        for (int k = 0; k < 18; k++) w[k] = wp[k];
    }
    const ull bias2 = pack2(g_bias[g][u], 0.0f);
    // activation: act = fma(S, tanh(S*x), D); cell gate (g==2) tanh, else sigmoid
    const float S = (g == 2) ? 1.0f : 0.5f;
    const float D = (g == 2) ? 0.0f : 0.5f;
    const int   isg0 = (g == 0);

    // zero v buffers (h must start at 0)
    for (int i = tid; i < 2 * BBLK * SVS; i += NTHR) (&sv[0][0][0])[i] = 0.0f;
    stage_x(X, 0, bbase + bgb, lt, &sv[0][0][0], bgb);

    float c[4] = {0.0f, 0.0f, 0.0f, 0.0f};

    __syncthreads();

    int cur = 0;
#pragma unroll 1
    for (int t = 0; t < SEQ; ++t) {
        if (t + 1 < SEQ) stage_x(X, t + 1, bbase + bgb, lt, &sv[cur ^ 1][0][0], bgb);

        float* hn = &sv[cur ^ 1][0][0];

#pragma unroll
        for (int p = 0; p < 2; ++p) {
            const float* v0 = &sv[cur][bgb + 2 * p][0];
            const float* v1 = &sv[cur][bgb + 2 * p + 1][0];
            ull a0 = bias2, a1 = bias2;
#pragma unroll
            for (int q = 0; q < NQ; ++q) {
                ulonglong2 V0 = *(const ulonglong2*)(v0 + 4 * q);  // warp-broadcast
                ulonglong2 V1 = *(const ulonglong2*)(v1 + 4 * q);
                ffma2(a0, w[2 * q],     V0.x);
                ffma2(a0, w[2 * q + 1], V0.y);
                ffma2(a1, w[2 * q],     V1.x);
                ffma2(a1, w[2 * q + 1], V1.y);
            }
            // own-gate activation
            float act0 = fmaf(S, tanh_fast(S * hsum2(a0)), D);
            float act1 = fmaf(S, tanh_fast(S * hsum2(a1)), D);
            // gate exchange: lane g=0 receives f (xor8), g (xor16), o (xor8^16)
            float f0 = __shfl_xor_sync(0xffffffffu, act0, 8);
            float G0 = __shfl_xor_sync(0xffffffffu, act0, 16);
            float o0 = __shfl_xor_sync(0xffffffffu, f0, 16);
            float f1 = __shfl_xor_sync(0xffffffffu, act1, 8);
            float G1 = __shfl_xor_sync(0xffffffffu, act1, 16);
            float o1 = __shfl_xor_sync(0xffffffffu, f1, 16);
            // c/h update: valid in g==0 lanes; all lanes compute (|f|<1 keeps bounded)
            c[2 * p]     = f0 * c[2 * p]     + act0 * G0;
            c[2 * p + 1] = f1 * c[2 * p + 1] + act1 * G1;
            float h0 = o0 * tanh_fast(c[2 * p]);
            float h1 = o1 * tanh_fast(c[2 * p + 1]);
            sts_if(isg0, hn + (bgb + 2 * p)     * SVS + INP + u, h0);
            sts_if(isg0, hn + (bgb + 2 * p + 1) * SVS + INP + u, h1);
        }

        asm volatile("bar.sync %0, %1;" :: "r"(barid), "n"(DTHR) : "memory");
        cur ^= 1;
    }

    // fused fc1+fc2 epilogue, per domain
    const float* hf = &sv[cur][0][0];
    for (int idx = lt; idx < DOMB * OUTD; idx += DTHR) {
        int b = idx / OUTD, o = idx % OUTD;
        float s = g_bv[o];
#pragma unroll
        for (int j = 0; j < HID; j++) s += hf[(bgb + b) * SVS + INP + j] * g_M[j][o];
        out[(size_t)(bbase + bgb + b) * OUTD + o] = s;
    }
}

// ---------------- launch ----------------
extern "C" void kernel_launch(void* const* d_in, const int* in_sizes, int n_in,
                              void* d_out, int out_size) {
    const float* X   = (const float*)d_in[0];
    const float* Wih = (const float*)d_in[1];
    const float* Whh = (const float*)d_in[2];
    const float* bih = (const float*)d_in[3];
    const float* bhh = (const float*)d_in[4];
    const float* W1  = (const float*)d_in[5];
    const float* b1  = (const float*)d_in[6];
    const float* W2  = (const float*)d_in[7];
    const float* b2  = (const float*)d_in[8];

    prep_kernel<<<1, 256>>>(Wih, Whh, bih, bhh, W1, b1, W2, b2);
    lstm_kernel<<<NBLK, NTHR>>>(X, (float*)d_out);
}

// round 6
// speedup vs baseline: 1.4988x; 1.4988x over previous
#include <cuda_runtime.h>

#define SEQ   600
#define BATCH 4096
#define INP   6
#define HID   30
#define OUTD  61
#define WROW  40              // g_W row stride in floats (160B)
#define NTHR  256             // 8 warps
#define WPB   8               // warps per block
#define BPW   4               // batches per warp
#define BBLK  (WPB * BPW)     // 32 batches per block
#define NBLK  (BATCH / BBLK)  // 128 blocks

typedef unsigned long long ull;

// ---------------- preprocessed weights (device globals) ----------------
__device__ __align__(16) float g_W[4][32][WROW];  // [gate][unit][ x(6) | h(30) | pad0(4) ]
__device__ float g_bias[4][32];                   // b_ih + b_hh (0 for pad units)
__device__ float g_M[HID][OUTD];                  // fused fc1+fc2
__device__ float g_bv[OUTD];                      // b2 + b1 @ W2^T

// ---------------- helpers ----------------
__device__ __forceinline__ void ffma2(ull& acc, ull a, ull b) {
    asm("fma.rn.f32x2 %0, %1, %2, %0;" : "+l"(acc) : "l"(a), "l"(b));
}
__device__ __forceinline__ ull pack2(float x, float y) {
    ull r; asm("mov.b64 %0, {%1, %2};" : "=l"(r) : "f"(x), "f"(y)); return r;
}
__device__ __forceinline__ float hsum2(ull v) {
    float2 r; asm("mov.b64 {%0, %1}, %2;" : "=f"(r.x), "=f"(r.y) : "l"(v));
    return r.x + r.y;
}
__device__ __forceinline__ float tanh_fast(float x) {
    float r; asm("tanh.approx.f32 %0, %1;" : "=f"(r) : "f"(x)); return r;
}
__device__ __forceinline__ float sigmoid_fast(float x) {
    return fmaf(0.5f, tanh_fast(0.5f * x), 0.5f);
}

// ---------------- prep kernel ----------------
__global__ void prep_kernel(const float* __restrict__ Wih, const float* __restrict__ Whh,
                            const float* __restrict__ bih, const float* __restrict__ bhh,
                            const float* __restrict__ W1,  const float* __restrict__ b1,
                            const float* __restrict__ W2,  const float* __restrict__ b2) {
    int tid = threadIdx.x;
    for (int idx = tid; idx < 4 * 32 * WROW; idx += blockDim.x) {
        int g = idx / (32 * WROW);
        int r = idx % (32 * WROW);
        int u = r / WROW, j = r % WROW;
        float w = 0.0f;
        if (u < HID) {
            if (j < INP)            w = Wih[(g * HID + u) * INP + j];
            else if (j < INP + HID) w = Whh[(g * HID + u) * HID + (j - INP)];
        }
        g_W[g][u][j] = w;
    }
    for (int idx = tid; idx < 4 * 32; idx += blockDim.x) {
        int g = idx / 32, u = idx % 32;
        g_bias[g][u] = (u < HID) ? (bih[g * HID + u] + bhh[g * HID + u]) : 0.0f;
    }
    for (int idx = tid; idx < HID * OUTD; idx += blockDim.x) {
        int j = idx / OUTD, o = idx % OUTD;
        float s = 0.0f;
        for (int k = 0; k < HID; k++) s += W1[k * HID + j] * W2[o * HID + k];
        g_M[j][o] = s;
    }
    for (int o = tid; o < OUTD; o += blockDim.x) {
        float s = b2[o];
        for (int k = 0; k < HID; k++) s += b1[k] * W2[o * HID + k];
        g_bv[o] = s;
    }
}

// ---------------- main persistent LSTM kernel (warp-autonomous) ----------------
__global__ void __launch_bounds__(NTHR, 1)
lstm_kernel(const float* __restrict__ X, float* __restrict__ out) {
    // per-warp state: h (single-buffered) and x (double-buffered)
    __shared__ __align__(16) float hb[WPB][BPW][32];     // 4096 B
    __shared__ __align__(16) float xb[WPB][2][BPW * INP];// 1536 B (24 floats/buf)

    const int tid    = threadIdx.x;
    const int lane   = tid & 31;                 // unit 0..31 (30 real, 2 pad)
    const int wid    = tid >> 5;                 // warp 0..7
    const int wg     = blockIdx.x * WPB + wid;   // global warp id
    const int bfirst = wg * BPW;                 // first global batch of this warp
    const bool xlane = (lane < BPW * INP / 4);   // lanes 0..5 stage x

    // ---- weights for (all 4 gates, unit=lane) into registers: 4 x 19 ull ----
    ull w[4][19];
    ull bias2[4];
#pragma unroll
    for (int g = 0; g < 4; g++) {
        const ull* wp = (const ull*)&g_W[g][lane][0];
#pragma unroll
        for (int k = 0; k < 19; k++) w[g][k] = wp[k];
        bias2[g] = pack2(g_bias[g][lane], 0.0f);
    }

    // ---- init: zero h, stage x(0) ----
#pragma unroll
    for (int b = 0; b < BPW; b++) hb[wid][b][lane] = 0.0f;
    if (xlane) {
        const float4 v = *(const float4*)(X + (size_t)bfirst * INP + lane * 4);
        *(float4*)&xb[wid][0][lane * 4] = v;
    }
    __syncwarp();

    float c[BPW] = {0.0f, 0.0f, 0.0f, 0.0f};

    int cur = 0;
#pragma unroll 1
    for (int t = 0; t < SEQ; ++t) {
        // prefetch x(t+1) into registers (clamped at the end; value unused then)
        float4 xp;
        const int tn = (t + 1 < SEQ) ? t + 1 : t;
        if (xlane)
            xp = *(const float4*)(X + ((size_t)tn * BATCH + bfirst) * INP + lane * 4);

        const float* xr = &xb[wid][cur][0];

#pragma unroll
        for (int b = 0; b < BPW; b++) {
            // v = [x(6) | h(30+2pad)] loads — all warp-uniform (broadcast)
            ull vx0 = *(const ull*)(xr + 6 * b);
            ull vx1 = *(const ull*)(xr + 6 * b + 2);
            ull vx2 = *(const ull*)(xr + 6 * b + 4);
            const ulonglong2* hr = (const ulonglong2*)&hb[wid][b][0];

            ull a0 = bias2[0], a1 = bias2[1], a2 = bias2[2], a3 = bias2[3];
            ffma2(a0, w[0][0], vx0); ffma2(a1, w[1][0], vx0);
            ffma2(a2, w[2][0], vx0); ffma2(a3, w[3][0], vx0);
            ffma2(a0, w[0][1], vx1); ffma2(a1, w[1][1], vx1);
            ffma2(a2, w[2][1], vx1); ffma2(a3, w[3][1], vx1);
            ffma2(a0, w[0][2], vx2); ffma2(a1, w[1][2], vx2);
            ffma2(a2, w[2][2], vx2); ffma2(a3, w[3][2], vx2);
#pragma unroll
            for (int k = 0; k < 8; k++) {
                ulonglong2 vh = hr[k];
                ffma2(a0, w[0][3 + 2 * k], vh.x); ffma2(a1, w[1][3 + 2 * k], vh.x);
                ffma2(a2, w[2][3 + 2 * k], vh.x); ffma2(a3, w[3][3 + 2 * k], vh.x);
                ffma2(a0, w[0][4 + 2 * k], vh.y); ffma2(a1, w[1][4 + 2 * k], vh.y);
                ffma2(a2, w[2][4 + 2 * k], vh.y); ffma2(a3, w[3][4 + 2 * k], vh.y);
            }
            // gates: i, f, g~, o — all in-thread
            float si = sigmoid_fast(hsum2(a0));
            float sf = sigmoid_fast(hsum2(a1));
            float tg = tanh_fast   (hsum2(a2));
            float so = sigmoid_fast(hsum2(a3));
            c[b] = fmaf(sf, c[b], si * tg);
            hb[wid][b][lane] = so * tanh_fast(c[b]);   // pad lanes write 0 naturally
        }

        // publish x(t+1) into the other x buffer
        if (xlane) *(float4*)&xb[wid][cur ^ 1][lane * 4] = xp;
        __syncwarp();   // cross-lane visibility of h(t) and x(t+1)
        cur ^= 1;
    }

    // ---- fused fc1+fc2 epilogue over the block's 32 batches ----
    __syncthreads();
    for (int idx = tid; idx < BBLK * OUTD; idx += NTHR) {
        int lb = idx / OUTD, o = idx % OUTD;
        int ww = lb / BPW, b = lb % BPW;
        float s = g_bv[o];
#pragma unroll
        for (int j = 0; j < HID; j++) s += hb[ww][b][j] * g_M[j][o];
        out[(size_t)(blockIdx.x * BBLK + lb) * OUTD + o] = s;
    }
}

// ---------------- launch ----------------
extern "C" void kernel_launch(void* const* d_in, const int* in_sizes, int n_in,
                              void* d_out, int out_size) {
    const float* X   = (const float*)d_in[0];
    const float* Wih = (const float*)d_in[1];
    const float* Whh = (const float*)d_in[2];
    const float* bih = (const float*)d_in[3];
    const float* bhh = (const float*)d_in[4];
    const float* W1  = (const float*)d_in[5];
    const float* b1  = (const float*)d_in[6];
    const float* W2  = (const float*)d_in[7];
    const float* b2  = (const float*)d_in[8];

    prep_kernel<<<1, 256>>>(Wih, Whh, bih, bhh, W1, b1, W2, b2);
    lstm_kernel<<<NBLK, NTHR>>>(X, (float*)d_out);
}